// round 8
// baseline (speedup 1.0000x reference)
#include <cuda_runtime.h>
#include <cuda_fp16.h>

// Problem constants (fixed by the reference)
#define NN      100000      // nodes
#define FF      32          // feats
#define CC      16          // classes
#define EE      1600000     // edges
#define EMB_DIM 6
#define HID     9
#define DEPTH   10
#define DIFF    0.9f
#define ODIFF   0.1f        // 1 - DIFF

#define NF  (NN * FF)
#define NH4 (NN * 4)        // uint4 (8 halfs) per node row of 32 halfs

// ---------------- device scratch (no allocs allowed) ----------------
__device__ int    g_cnt[NN];
__device__ int    g_cur[NN];
__device__ int    g_rowptr[NN + 1];
__device__ int    g_col[EE];
__device__ float  g_invdeg[NN];
__device__ float  g_isd[NN];   // rsqrt(max(deg,1))
__device__ float  g_sqd[NN];   // sqrt(max(deg,1))
__device__ uint4  g_h0[NH4];   // u0 in half (row = 32 halfs = 64B)
__device__ uint4  g_ha[NH4];   // ping
__device__ uint4  g_hb[NH4];   // pong
__device__ float  g_uf[NF];    // fp32 final result of each diffuse phase

__device__ __forceinline__ uint4* hbuf(int sel) {
    return (sel == 0) ? g_h0 : (sel == 1) ? g_ha : g_hb;
}

__device__ __forceinline__ void add8(float* a, uint4 v) {
    const half2* h = reinterpret_cast<const half2*>(&v);
    float2 f0 = __half22float2(h[0]);
    float2 f1 = __half22float2(h[1]);
    float2 f2 = __half22float2(h[2]);
    float2 f3 = __half22float2(h[3]);
    a[0] += f0.x; a[1] += f0.y;
    a[2] += f1.x; a[3] += f1.y;
    a[4] += f2.x; a[5] += f2.y;
    a[6] += f3.x; a[7] += f3.y;
}

__device__ __forceinline__ void unpack8(float* a, uint4 v) {
    const half2* h = reinterpret_cast<const half2*>(&v);
    float2 f0 = __half22float2(h[0]);
    float2 f1 = __half22float2(h[1]);
    float2 f2 = __half22float2(h[2]);
    float2 f3 = __half22float2(h[3]);
    a[0] = f0.x; a[1] = f0.y;
    a[2] = f1.x; a[3] = f1.y;
    a[4] = f2.x; a[5] = f2.y;
    a[6] = f3.x; a[7] = f3.y;
}

__device__ __forceinline__ uint4 pack8(const float* a) {
    uint4 r;
    half2* h = reinterpret_cast<half2*>(&r);
    h[0] = __floats2half2_rn(a[0], a[1]);
    h[1] = __floats2half2_rn(a[2], a[3]);
    h[2] = __floats2half2_rn(a[4], a[5]);
    h[3] = __floats2half2_rn(a[6], a[7]);
    return r;
}

// ---------------- kernels ----------------

// counts dst degrees; also zeroes g_cur (used only later by k_fill)
__global__ void k_count(const int* __restrict__ edges) {
    int e = blockIdx.x * blockDim.x + threadIdx.x;
    if (e < NN) g_cur[e] = 0;
    if (e < EE) {
        int d = edges[EE + e];
        if ((unsigned)d < (unsigned)NN)
            atomicAdd(&g_cnt[d], 1);
    }
}

// single-block exclusive scan of g_cnt -> g_rowptr, plus per-node scalars
__global__ void k_scan() {
    const int T = 1024;
    int tid = threadIdx.x;
    int chunk = (NN + T - 1) / T;                 // 98
    int beg = tid * chunk;
    int end = beg + chunk; if (end > NN) end = NN;
    if (beg > NN) beg = NN;

    int sum = 0;
    for (int i = beg; i < end; i++) sum += g_cnt[i];

    __shared__ int sh[T];
    sh[tid] = sum;
    __syncthreads();
    for (int off = 1; off < T; off <<= 1) {
        int v = (tid >= off) ? sh[tid - off] : 0;
        __syncthreads();
        sh[tid] += v;
        __syncthreads();
    }
    int run = (tid == 0) ? 0 : sh[tid - 1];       // exclusive prefix
    for (int i = beg; i < end; i++) {
        g_rowptr[i] = run;
        int c = g_cnt[i];
        run += c;
        float d   = (c > 0) ? (float)c : 1.0f;
        float isd = rsqrtf(d);
        g_invdeg[i] = 1.0f / d;
        g_isd[i]    = isd;
        g_sqd[i]    = sqrtf(d);
    }
    if (tid == T - 1) g_rowptr[NN] = run;         // == EE
}

// u0 = x * rsqrt(deg) stored as half2 (scalars already computed by k_scan)
__global__ void k_prep(const float* __restrict__ x) {
    int idx2 = blockIdx.x * blockDim.x + threadIdx.x;   // half2 index
    if (idx2 >= NF / 2) return;
    int n = idx2 >> 4;
    float isd = g_isd[n];
    float2 xv = reinterpret_cast<const float2*>(x)[idx2];
    reinterpret_cast<half2*>(g_h0)[idx2] = __floats2half2_rn(xv.x * isd, xv.y * isd);
}

__global__ void k_fill(const int* __restrict__ edges) {
    int e = blockIdx.x * blockDim.x + threadIdx.x;
    if (e < EE) {
        int s = edges[e];
        int d = edges[EE + e];
        if ((unsigned)d < (unsigned)NN && (unsigned)s < (unsigned)NN) {
            int pos = g_rowptr[d] + atomicAdd(&g_cur[d], 1);
            g_col[pos] = s;
        }
    }
}

// One warp per dst node. 8 groups of 4 lanes; lane loads uint4 = 8 halfs of
// the 64B half row. Group g owns predicated neighbor slots beg+g+8k, k=0..7
// (straight-line for deg <= 64; rare overflow loops). 8 independent idx loads
// then 8 independent value loads in flight per lane; disabled slots add +0.0.
// fp32 accumulate, 3-stage shfl combine across groups.
// OUT_HALF: write half row to hbuf(out_sel); else fp32 row to g_uf.
template <bool OUT_HALF>
__global__ void __launch_bounds__(256) k_conv(int in_sel, int out_sel) {
    const uint4* __restrict__ u_in = hbuf(in_sel);

    int node = (blockIdx.x * blockDim.x + threadIdx.x) >> 5;
    if (node >= NN) return;
    int lane = threadIdx.x & 31;
    int grp  = lane >> 2;     // neighbor group 0..7
    int sl   = lane & 3;      // uint4 slot within row 0..3

    int beg = g_rowptr[node];
    int end = g_rowptr[node + 1];
    int j0  = beg + grp;

    // 8 predicated slots at stride 8 (covers deg <= 64 branch-free)
    int  idx[8];
    bool p[8];
    #pragma unroll
    for (int k = 0; k < 8; k++) {
        int j = j0 + 8 * k;
        p[k]   = (j < end);
        idx[k] = p[k] ? __ldg(&g_col[j]) : 0;
    }
    uint4 v[8];
    const uint4 z = make_uint4(0u, 0u, 0u, 0u);   // half bits 0 == +0.0
    #pragma unroll
    for (int k = 0; k < 8; k++)
        v[k] = p[k] ? __ldg(&u_in[idx[k] * 4 + sl]) : z;

    float acc[8] = {0.f, 0.f, 0.f, 0.f, 0.f, 0.f, 0.f, 0.f};
    #pragma unroll
    for (int k = 0; k < 8; k++)
        add8(acc, v[k]);

    // rare: deg > 64
    for (int j = j0 + 64; j < end; j += 8)
        add8(acc, __ldg(&u_in[__ldg(&g_col[j]) * 4 + sl]));

    // combine 8 group partials (lanes with equal sl): xor bits 2,3,4
    #pragma unroll
    for (int off = 4; off <= 16; off <<= 1) {
        #pragma unroll
        for (int k = 0; k < 8; k++)
            acc[k] += __shfl_xor_sync(0xffffffffu, acc[k], off);
    }

    if (grp == 0) {
        float w = DIFF * __ldg(&g_invdeg[node]);
        float h0[8];
        unpack8(h0, __ldg(&g_h0[node * 4 + sl]));
        float r[8];
        #pragma unroll
        for (int k = 0; k < 8; k++)
            r[k] = fmaf(w, acc[k], ODIFF * h0[k]);
        if (OUT_HALF) {
            hbuf(out_sel)[node * 4 + sl] = pack8(r);
        } else {
            float4* o = reinterpret_cast<float4*>(g_uf);
            o[node * 8 + sl * 2 + 0] = make_float4(r[0], r[1], r[2], r[3]);
            o[node * 8 + sl * 2 + 1] = make_float4(r[4], r[5], r[6], r[7]);
        }
    }
}

// per-(node,feature) MLP elementwise, rescaled in/out of u-space.
// Reads g_uf (fp32), writes new u0 (half) into g_h0. Two feats per thread.
__global__ void k_mlp(const float* __restrict__ emb,
                      const float* __restrict__ W1,
                      const float* __restrict__ b1,
                      const float* __restrict__ W2,
                      const float* __restrict__ b2) {
    __shared__ float sA[HID];           // W1 row 0
    __shared__ float sW2[HID];
    __shared__ float sC[FF][HID];       // b1[j] + sum_d emb[f,d]*W1[1+d,j]
    __shared__ float sB2;

    for (int t = threadIdx.x; t < FF * HID; t += blockDim.x) {
        int f = t / HID, j = t % HID;
        float c = b1[j];
        #pragma unroll
        for (int d = 0; d < EMB_DIM; d++)
            c += emb[f * EMB_DIM + d] * W1[(1 + d) * HID + j];
        sC[f][j] = c;
    }
    if (threadIdx.x < HID) {
        sA[threadIdx.x]  = W1[threadIdx.x];      // row 0
        sW2[threadIdx.x] = W2[threadIdx.x];
    }
    if (threadIdx.x == 0) sB2 = b2[0];
    __syncthreads();

    int idx2 = blockIdx.x * blockDim.x + threadIdx.x;   // half2 index
    if (idx2 >= NF / 2) return;
    int n  = idx2 >> 4;
    int f0 = (idx2 & 15) * 2;
    float sq  = g_sqd[n];
    float isd = g_isd[n];
    float2 tv = reinterpret_cast<const float2*>(g_uf)[idx2];
    float t0 = tv.x * sq, t1 = tv.y * sq;
    float r0 = sB2, r1 = sB2;
    #pragma unroll
    for (int j = 0; j < HID; j++) {
        float h0 = fmaf(sA[j], t0, sC[f0][j]);
        float h1 = fmaf(sA[j], t1, sC[f0 + 1][j]);
        r0 = fmaf(sW2[j], fmaxf(h0, 0.0f), r0);
        r1 = fmaf(sW2[j], fmaxf(h1, 0.0f), r1);
    }
    reinterpret_cast<half2*>(g_h0)[idx2] = __floats2half2_rn(r0 * isd, r1 * isd);
}

// out[n,c] = bout[c] + sum_k (g_uf[n,k]*sqd[n]) * Wout[k,c]
__global__ void k_out(const float* __restrict__ Wout,
                      const float* __restrict__ bout,
                      float* __restrict__ out) {
    __shared__ float sW[FF * CC];
    __shared__ float sb[CC];
    for (int t = threadIdx.x; t < FF * CC; t += blockDim.x) sW[t] = Wout[t];
    if (threadIdx.x < CC) sb[threadIdx.x] = bout[threadIdx.x];
    __syncthreads();

    int tid = blockIdx.x * blockDim.x + threadIdx.x;
    if (tid >= NN * CC) return;
    int n = tid >> 4;
    int c = tid & 15;
    float sd = g_sqd[n];
    float acc = sb[c];
    #pragma unroll
    for (int k = 0; k < FF; k++)
        acc = fmaf(g_uf[n * 32 + k] * sd, sW[k * CC + c], acc);
    out[tid] = acc;
}

// ---------------- launch ----------------

static void diffuse(int gC, int TB) {
    // step 1: u0(half, sel 0) -> ha(1)
    k_conv<true><<<gC, TB>>>(0, 1);
    // steps 2..9: ping-pong ha(1)/hb(2)
    for (int i = 2; i < DEPTH; i++) {
        int in_sel  = (i & 1) ? 2 : 1;
        int out_sel = (i & 1) ? 1 : 2;
        k_conv<true><<<gC, TB>>>(in_sel, out_sel);
    }
    // step 10: in = ha(1) (step 9 wrote sel 1) -> fp32 g_uf
    k_conv<false><<<gC, TB>>>(1, 0 /*unused*/);
}

extern "C" void kernel_launch(void* const* d_in, const int* in_sizes, int n_in,
                              void* d_out, int out_size) {
    const float* x     = (const float*)d_in[0];
    const int*   edges = (const int*)d_in[1];       // int32 per harness dtype contract
    const float* emb   = (const float*)d_in[2];
    const float* W1    = (const float*)d_in[3];
    const float* b1    = (const float*)d_in[4];
    const float* W2    = (const float*)d_in[5];
    const float* b2    = (const float*)d_in[6];
    const float* Wout  = (const float*)d_in[7];
    const float* bout  = (const float*)d_in[8];
    float* out = (float*)d_out;

    const int TB = 256;
    int gE  = (EE + TB - 1) / TB;
    int gH2 = (NF / 2 + TB - 1) / TB;            // half2-element grid
    int gC  = (NN * 32 + TB - 1) / TB;           // warp-per-node conv grid
    int gNC = (NN * CC + TB - 1) / TB;

    // CSR build (g_cnt via async memset; g_cur zeroed inside k_count)
    void* cntp = nullptr;
    cudaGetSymbolAddress(&cntp, g_cnt);
    cudaMemsetAsync(cntp, 0, NN * sizeof(int));
    k_count<<<gE, TB>>>(edges);
    k_scan<<<1, 1024>>>();
    k_prep<<<gH2, TB>>>(x);
    k_fill<<<gE, TB>>>(edges);

    // diffuse 1 -> g_uf (fp32)
    diffuse(gC, TB);

    // per-element MLP (reads g_uf, writes new half u0 into g_h0)
    k_mlp<<<gH2, TB>>>(emb, W1, b1, W2, b2);

    // diffuse 2 -> g_uf (fp32)
    diffuse(gC, TB);

    // output GEMM
    k_out<<<gNC, TB>>>(Wout, bout, out);
}

// round 9
// speedup vs baseline: 1.2055x; 1.2055x over previous
#include <cuda_runtime.h>
#include <cuda_bf16.h>

// Problem constants (fixed by the reference)
#define NN      100000      // nodes
#define FF      32          // feats
#define CC      16          // classes
#define EE      1600000     // edges
#define EMB_DIM 6
#define HID     9
#define DEPTH   10
#define DIFF    0.9f
#define ODIFF   0.1f        // 1 - DIFF

#define NF  (NN * FF)
#define NF4 (NF / 4)        // float4 elements per u buffer

// ---------------- device scratch (no allocs allowed) ----------------
__device__ int    g_cnt[NN];
__device__ int    g_cur[NN];
__device__ int    g_rowptr[NN + 1];
__device__ int    g_col[EE];
__device__ float  g_invdeg[NN];
__device__ float  g_isd[NN];   // rsqrt(max(deg,1))
__device__ float  g_sqd[NN];   // sqrt(max(deg,1))
__device__ float4 g_u0v[NF4];  // fp32 u buffers (row = 32 floats = 128B)
__device__ float4 g_uav[NF4];
__device__ float4 g_ubv[NF4];

__device__ __forceinline__ float4* bufv(int sel) {
    return (sel == 0) ? g_u0v : (sel == 1) ? g_uav : g_ubv;
}

// ---------------- kernels ----------------

// degree count, 4 edges per thread via int4 (EE % 4 == 0; dst row 16B aligned)
__global__ void k_count(const int* __restrict__ edges) {
    int t = blockIdx.x * blockDim.x + threadIdx.x;
    if (t >= EE / 4) return;
    int4 d4 = __ldg(&reinterpret_cast<const int4*>(edges + EE)[t]);
    if ((unsigned)d4.x < (unsigned)NN) atomicAdd(&g_cnt[d4.x], 1);
    if ((unsigned)d4.y < (unsigned)NN) atomicAdd(&g_cnt[d4.y], 1);
    if ((unsigned)d4.z < (unsigned)NN) atomicAdd(&g_cnt[d4.z], 1);
    if ((unsigned)d4.w < (unsigned)NN) atomicAdd(&g_cnt[d4.w], 1);
}

// single-block exclusive scan of g_cnt -> g_rowptr, plus per-node scalars
__global__ void k_scan() {
    const int T = 1024;
    int tid = threadIdx.x;
    int chunk = (NN + T - 1) / T;                 // 98
    int beg = tid * chunk;
    int end = beg + chunk; if (end > NN) end = NN;
    if (beg > NN) beg = NN;

    int sum = 0;
    for (int i = beg; i < end; i++) sum += g_cnt[i];

    __shared__ int sh[T];
    sh[tid] = sum;
    __syncthreads();
    for (int off = 1; off < T; off <<= 1) {
        int v = (tid >= off) ? sh[tid - off] : 0;
        __syncthreads();
        sh[tid] += v;
        __syncthreads();
    }
    int run = (tid == 0) ? 0 : sh[tid - 1];       // exclusive prefix
    for (int i = beg; i < end; i++) {
        g_rowptr[i] = run;
        int c = g_cnt[i];
        run += c;
        float d   = (c > 0) ? (float)c : 1.0f;
        float isd = rsqrtf(d);
        g_invdeg[i] = 1.0f / d;
        g_isd[i]    = isd;
        g_sqd[i]    = sqrtf(d);
    }
    if (tid == T - 1) g_rowptr[NN] = run;         // == EE
}

// u0 = x * rsqrt(deg) (scalars already computed by k_scan)
__global__ void k_prep(const float* __restrict__ x) {
    int idx = blockIdx.x * blockDim.x + threadIdx.x;
    if (idx >= NF) return;
    int n = idx >> 5;
    ((float*)g_u0v)[idx] = x[idx] * g_isd[n];
}

// CSR fill, 4 edges per thread via int4
__global__ void k_fill(const int* __restrict__ edges) {
    int t = blockIdx.x * blockDim.x + threadIdx.x;
    if (t >= EE / 4) return;
    int4 s4 = __ldg(&reinterpret_cast<const int4*>(edges)[t]);
    int4 d4 = __ldg(&reinterpret_cast<const int4*>(edges + EE)[t]);
    if ((unsigned)d4.x < (unsigned)NN && (unsigned)s4.x < (unsigned)NN)
        g_col[g_rowptr[d4.x] + atomicAdd(&g_cur[d4.x], 1)] = s4.x;
    if ((unsigned)d4.y < (unsigned)NN && (unsigned)s4.y < (unsigned)NN)
        g_col[g_rowptr[d4.y] + atomicAdd(&g_cur[d4.y], 1)] = s4.y;
    if ((unsigned)d4.z < (unsigned)NN && (unsigned)s4.z < (unsigned)NN)
        g_col[g_rowptr[d4.z] + atomicAdd(&g_cur[d4.z], 1)] = s4.z;
    if ((unsigned)d4.w < (unsigned)NN && (unsigned)s4.w < (unsigned)NN)
        g_col[g_rowptr[d4.w] + atomicAdd(&g_cur[d4.w], 1)] = s4.w;
}

// one warp per dst node; 4 groups of 8 lanes; group g gathers neighbor j+g
// as 8x float4 (full 128B row per group). Butterfly-combine groups at end.
// u_out[n,:] = 0.9 * invdeg[n] * sum_{s in N(n)} u_in[s,:] + 0.1 * u0[n,:]
__global__ void __launch_bounds__(256) k_conv(int in_sel, int out_sel) {
    const float4* __restrict__ u_in  = bufv(in_sel);
    float4* __restrict__       u_out = bufv(out_sel);

    int gwarp = (blockIdx.x * blockDim.x + threadIdx.x) >> 5;
    if (gwarp >= NN) return;
    int lane = threadIdx.x & 31;
    int sub  = lane >> 3;      // neighbor group 0..3
    int fl   = lane & 7;       // float4 slot within row 0..7

    int beg = g_rowptr[gwarp];
    int end = g_rowptr[gwarp + 1];

    float4 acc = make_float4(0.f, 0.f, 0.f, 0.f);
    int j = beg + sub;
    // main: 16 neighbors per iteration (4 per group), 4 independent LDG.128/lane
    for (; j + 12 < end; j += 16) {
        int s0 = __ldg(&g_col[j]);
        int s1 = __ldg(&g_col[j + 4]);
        int s2 = __ldg(&g_col[j + 8]);
        int s3 = __ldg(&g_col[j + 12]);
        float4 v0 = __ldg(&u_in[s0 * 8 + fl]);
        float4 v1 = __ldg(&u_in[s1 * 8 + fl]);
        float4 v2 = __ldg(&u_in[s2 * 8 + fl]);
        float4 v3 = __ldg(&u_in[s3 * 8 + fl]);
        acc.x += v0.x + v1.x + v2.x + v3.x;
        acc.y += v0.y + v1.y + v2.y + v3.y;
        acc.z += v0.z + v1.z + v2.z + v3.z;
        acc.w += v0.w + v1.w + v2.w + v3.w;
    }
    // tail: each group advances by 4, self-predicated
    for (; j < end; j += 4) {
        int s = __ldg(&g_col[j]);
        float4 v = __ldg(&u_in[s * 8 + fl]);
        acc.x += v.x; acc.y += v.y; acc.z += v.z; acc.w += v.w;
    }

    // combine the 4 group partials (lanes with equal fl across groups)
    #pragma unroll
    for (int off = 8; off < 32; off <<= 1) {
        acc.x += __shfl_xor_sync(0xffffffffu, acc.x, off);
        acc.y += __shfl_xor_sync(0xffffffffu, acc.y, off);
        acc.z += __shfl_xor_sync(0xffffffffu, acc.z, off);
        acc.w += __shfl_xor_sync(0xffffffffu, acc.w, off);
    }

    if (sub == 0) {
        float  w  = DIFF * g_invdeg[gwarp];
        float4 h0 = __ldg(&g_u0v[gwarp * 8 + fl]);
        float4 r;
        r.x = fmaf(w, acc.x, ODIFF * h0.x);
        r.y = fmaf(w, acc.y, ODIFF * h0.y);
        r.z = fmaf(w, acc.z, ODIFF * h0.z);
        r.w = fmaf(w, acc.w, ODIFF * h0.w);
        u_out[gwarp * 8 + fl] = r;
    }
}

// per-(node,feature) MLP applied elementwise, with rescale in/out of u-space.
// Reads g_ubv, writes new u0 (= mlp_out * isd) into g_u0v.
__global__ void k_mlp(const float* __restrict__ emb,
                      const float* __restrict__ W1,
                      const float* __restrict__ b1,
                      const float* __restrict__ W2,
                      const float* __restrict__ b2) {
    __shared__ float sA[HID];           // W1 row 0
    __shared__ float sW2[HID];
    __shared__ float sC[FF][HID];       // b1[j] + sum_d emb[f,d]*W1[1+d,j]
    __shared__ float sB2;

    for (int t = threadIdx.x; t < FF * HID; t += blockDim.x) {
        int f = t / HID, j = t % HID;
        float c = b1[j];
        #pragma unroll
        for (int d = 0; d < EMB_DIM; d++)
            c += emb[f * EMB_DIM + d] * W1[(1 + d) * HID + j];
        sC[f][j] = c;
    }
    if (threadIdx.x < HID) {
        sA[threadIdx.x]  = W1[threadIdx.x];      // row 0
        sW2[threadIdx.x] = W2[threadIdx.x];
    }
    if (threadIdx.x == 0) sB2 = b2[0];
    __syncthreads();

    int idx = blockIdx.x * blockDim.x + threadIdx.x;
    if (idx >= NF) return;
    int n = idx >> 5;
    int f = idx & 31;
    float t = ((const float*)g_ubv)[idx] * g_sqd[n];
    float r = sB2;
    #pragma unroll
    for (int j = 0; j < HID; j++) {
        float h = fmaf(sA[j], t, sC[f][j]);
        r = fmaf(sW2[j], fmaxf(h, 0.0f), r);
    }
    ((float*)g_u0v)[idx] = r * g_isd[n];
}

// out[n,c] = bout[c] + sum_k (ub[n,k]*sqd[n]) * Wout[k,c]
__global__ void k_out(const float* __restrict__ Wout,
                      const float* __restrict__ bout,
                      float* __restrict__ out) {
    __shared__ float sW[FF * CC];
    __shared__ float sb[CC];
    for (int t = threadIdx.x; t < FF * CC; t += blockDim.x) sW[t] = Wout[t];
    if (threadIdx.x < CC) sb[threadIdx.x] = bout[threadIdx.x];
    __syncthreads();

    int tid = blockIdx.x * blockDim.x + threadIdx.x;
    if (tid >= NN * CC) return;
    int n = tid >> 4;
    int c = tid & 15;
    float sd = g_sqd[n];
    const float* u = (const float*)g_ubv;
    float acc = sb[c];
    #pragma unroll
    for (int k = 0; k < FF; k++)
        acc = fmaf(u[n * 32 + k] * sd, sW[k * CC + c], acc);
    out[tid] = acc;
}

// ---------------- launch ----------------

extern "C" void kernel_launch(void* const* d_in, const int* in_sizes, int n_in,
                              void* d_out, int out_size) {
    const float* x     = (const float*)d_in[0];
    const int*   edges = (const int*)d_in[1];       // int32 per harness dtype contract
    const float* emb   = (const float*)d_in[2];
    const float* W1    = (const float*)d_in[3];
    const float* b1    = (const float*)d_in[4];
    const float* W2    = (const float*)d_in[5];
    const float* b2    = (const float*)d_in[6];
    const float* Wout  = (const float*)d_in[7];
    const float* bout  = (const float*)d_in[8];
    float* out = (float*)d_out;

    const int TB = 256;
    int gE4 = (EE / 4 + TB - 1) / TB;
    int gNF = (NF + TB - 1) / TB;
    int gW  = (NN * 32 + TB - 1) / TB;   // warp-per-node grid
    int gNC = (NN * CC + TB - 1) / TB;

    // CSR build: counters zeroed via async memset, int4-vectorized passes
    void* cntp = nullptr; cudaGetSymbolAddress(&cntp, g_cnt);
    void* curp = nullptr; cudaGetSymbolAddress(&curp, g_cur);
    cudaMemsetAsync(cntp, 0, NN * sizeof(int));
    cudaMemsetAsync(curp, 0, NN * sizeof(int));
    k_count<<<gE4, TB>>>(edges);
    k_scan<<<1, 1024>>>();
    k_prep<<<gNF, TB>>>(x);
    k_fill<<<gE4, TB>>>(edges);

    // diffuse 1: u starts at u0 (sel 0); 10 conv steps ping-pong ua(1)/ub(2) -> ends in ub
    k_conv<<<gW, TB>>>(0, 1);
    for (int i = 1; i < DEPTH; i++) {
        int in_sel  = (i & 1) ? 1 : 2;
        int out_sel = (i & 1) ? 2 : 1;
        k_conv<<<gW, TB>>>(in_sel, out_sel);
    }

    // per-element MLP (reads g_ubv, writes new u0)
    k_mlp<<<gNF, TB>>>(emb, W1, b1, W2, b2);

    // diffuse 2
    k_conv<<<gW, TB>>>(0, 1);
    for (int i = 1; i < DEPTH; i++) {
        int in_sel  = (i & 1) ? 1 : 2;
        int out_sel = (i & 1) ? 2 : 1;
        k_conv<<<gW, TB>>>(in_sel, out_sel);
    }

    // output GEMM
    k_out<<<gNC, TB>>>(Wout, bout, out);
}

// round 13
// speedup vs baseline: 1.3041x; 1.0818x over previous
#include <cuda_runtime.h>
#include <cuda_bf16.h>

// Problem constants (fixed by the reference)
#define NN      100000      // nodes
#define FF      32          // feats
#define CC      16          // classes
#define EE      1600000     // edges
#define EMB_DIM 6
#define HID     9
#define DEPTH   10
#define DIFF    0.9f
#define ODIFF   0.1f        // 1 - DIFF

#define NF  (NN * FF)
#define NF4 (NF / 4)        // float4 elements per u buffer

// ---------------- device scratch (no allocs allowed) ----------------
__device__ int    g_cnt[NN];
__device__ int    g_cur[NN];
__device__ int    g_rowptr[NN + 1];
__device__ int    g_col[EE];
__device__ float  g_invdeg[NN];
__device__ float  g_isd[NN];   // rsqrt(max(deg,1))
__device__ float  g_sqd[NN];   // sqrt(max(deg,1))
__device__ float4 g_u0v[NF4];  // fp32 u buffers (row = 32 floats = 128B)
__device__ float4 g_uav[NF4];
__device__ float4 g_ubv[NF4];

__device__ __forceinline__ float4* bufv(int sel) {
    return (sel == 0) ? g_u0v : (sel == 1) ? g_uav : g_ubv;
}

// ---------------- kernels ----------------

// degree count, 4 edges per thread via int4 (EE % 4 == 0)
__global__ void k_count(const int* __restrict__ edges) {
    int t = blockIdx.x * blockDim.x + threadIdx.x;
    if (t >= EE / 4) return;
    int4 d4 = __ldg(&reinterpret_cast<const int4*>(edges + EE)[t]);
    if ((unsigned)d4.x < (unsigned)NN) atomicAdd(&g_cnt[d4.x], 1);
    if ((unsigned)d4.y < (unsigned)NN) atomicAdd(&g_cnt[d4.y], 1);
    if ((unsigned)d4.z < (unsigned)NN) atomicAdd(&g_cnt[d4.z], 1);
    if ((unsigned)d4.w < (unsigned)NN) atomicAdd(&g_cnt[d4.w], 1);
}

// single-block exclusive scan of g_cnt -> g_rowptr, plus per-node scalars
__global__ void k_scan() {
    const int T = 1024;
    int tid = threadIdx.x;
    int chunk = (NN + T - 1) / T;                 // 98
    int beg = tid * chunk;
    int end = beg + chunk; if (end > NN) end = NN;
    if (beg > NN) beg = NN;

    int sum = 0;
    for (int i = beg; i < end; i++) sum += g_cnt[i];

    __shared__ int sh[T];
    sh[tid] = sum;
    __syncthreads();
    for (int off = 1; off < T; off <<= 1) {
        int v = (tid >= off) ? sh[tid - off] : 0;
        __syncthreads();
        sh[tid] += v;
        __syncthreads();
    }
    int run = (tid == 0) ? 0 : sh[tid - 1];       // exclusive prefix
    for (int i = beg; i < end; i++) {
        g_rowptr[i] = run;
        int c = g_cnt[i];
        run += c;
        float d   = (c > 0) ? (float)c : 1.0f;
        float isd = rsqrtf(d);
        g_invdeg[i] = 1.0f / d;
        g_isd[i]    = isd;
        g_sqd[i]    = sqrtf(d);
    }
    if (tid == T - 1) g_rowptr[NN] = run;         // == EE
}

// u0 = x * rsqrt(deg) (scalars already computed by k_scan)
__global__ void k_prep(const float* __restrict__ x) {
    int idx = blockIdx.x * blockDim.x + threadIdx.x;
    if (idx >= NF) return;
    int n = idx >> 5;
    ((float*)g_u0v)[idx] = x[idx] * g_isd[n];
}

// CSR fill, 4 edges per thread via int4
__global__ void k_fill(const int* __restrict__ edges) {
    int t = blockIdx.x * blockDim.x + threadIdx.x;
    if (t >= EE / 4) return;
    int4 s4 = __ldg(&reinterpret_cast<const int4*>(edges)[t]);
    int4 d4 = __ldg(&reinterpret_cast<const int4*>(edges + EE)[t]);
    if ((unsigned)d4.x < (unsigned)NN && (unsigned)s4.x < (unsigned)NN)
        g_col[g_rowptr[d4.x] + atomicAdd(&g_cur[d4.x], 1)] = s4.x;
    if ((unsigned)d4.y < (unsigned)NN && (unsigned)s4.y < (unsigned)NN)
        g_col[g_rowptr[d4.y] + atomicAdd(&g_cur[d4.y], 1)] = s4.y;
    if ((unsigned)d4.z < (unsigned)NN && (unsigned)s4.z < (unsigned)NN)
        g_col[g_rowptr[d4.z] + atomicAdd(&g_cur[d4.z], 1)] = s4.z;
    if ((unsigned)d4.w < (unsigned)NN && (unsigned)s4.w < (unsigned)NN)
        g_col[g_rowptr[d4.w] + atomicAdd(&g_cur[d4.w], 1)] = s4.w;
}

// one warp per dst node; 4 groups of 8 lanes; group g gathers neighbor j+g
// as 8x float4 (full 128B row per group). Tail = one predicated 3-slot batch
// (independent loads, no serial chain). Butterfly-combine groups at end.
// u_out[n,:] = 0.9 * invdeg[n] * sum_{s in N(n)} u_in[s,:] + 0.1 * u0[n,:]
__global__ void __launch_bounds__(256) k_conv(int in_sel, int out_sel) {
    const float4* __restrict__ u_in  = bufv(in_sel);
    float4* __restrict__       u_out = bufv(out_sel);

    int gwarp = (blockIdx.x * blockDim.x + threadIdx.x) >> 5;
    if (gwarp >= NN) return;
    int lane = threadIdx.x & 31;
    int sub  = lane >> 3;      // neighbor group 0..3
    int fl   = lane & 7;       // float4 slot within row 0..7

    int beg = g_rowptr[gwarp];
    int end = g_rowptr[gwarp + 1];

    float4 acc = make_float4(0.f, 0.f, 0.f, 0.f);
    int j = beg + sub;
    // main: 16 neighbors per iteration (4 per group), 4 independent LDG.128/lane
    for (; j + 12 < end; j += 16) {
        int s0 = __ldg(&g_col[j]);
        int s1 = __ldg(&g_col[j + 4]);
        int s2 = __ldg(&g_col[j + 8]);
        int s3 = __ldg(&g_col[j + 12]);
        float4 v0 = __ldg(&u_in[s0 * 8 + fl]);
        float4 v1 = __ldg(&u_in[s1 * 8 + fl]);
        float4 v2 = __ldg(&u_in[s2 * 8 + fl]);
        float4 v3 = __ldg(&u_in[s3 * 8 + fl]);
        acc.x += v0.x + v1.x + v2.x + v3.x;
        acc.y += v0.y + v1.y + v2.y + v3.y;
        acc.z += v0.z + v1.z + v2.z + v3.z;
        acc.w += v0.w + v1.w + v2.w + v3.w;
    }
    // predicated tail: at most 3 neighbors remain per group, all independent
    {
        bool p0 = (j     < end);
        bool p1 = (j + 4 < end);
        bool p2 = (j + 8 < end);
        int s0 = p0 ? __ldg(&g_col[j])     : 0;
        int s1 = p1 ? __ldg(&g_col[j + 4]) : 0;
        int s2 = p2 ? __ldg(&g_col[j + 8]) : 0;
        const float4 z = make_float4(0.f, 0.f, 0.f, 0.f);
        float4 v0 = p0 ? __ldg(&u_in[s0 * 8 + fl]) : z;
        float4 v1 = p1 ? __ldg(&u_in[s1 * 8 + fl]) : z;
        float4 v2 = p2 ? __ldg(&u_in[s2 * 8 + fl]) : z;
        acc.x += v0.x + v1.x + v2.x;
        acc.y += v0.y + v1.y + v2.y;
        acc.z += v0.z + v1.z + v2.z;
        acc.w += v0.w + v1.w + v2.w;
    }

    // combine the 4 group partials (lanes with equal fl across groups)
    #pragma unroll
    for (int off = 8; off < 32; off <<= 1) {
        acc.x += __shfl_xor_sync(0xffffffffu, acc.x, off);
        acc.y += __shfl_xor_sync(0xffffffffu, acc.y, off);
        acc.z += __shfl_xor_sync(0xffffffffu, acc.z, off);
        acc.w += __shfl_xor_sync(0xffffffffu, acc.w, off);
    }

    if (sub == 0) {
        float  w  = DIFF * g_invdeg[gwarp];
        float4 h0 = __ldg(&g_u0v[gwarp * 8 + fl]);
        float4 r;
        r.x = fmaf(w, acc.x, ODIFF * h0.x);
        r.y = fmaf(w, acc.y, ODIFF * h0.y);
        r.z = fmaf(w, acc.z, ODIFF * h0.z);
        r.w = fmaf(w, acc.w, ODIFF * h0.w);
        u_out[gwarp * 8 + fl] = r;
    }
}

// per-(node,feature) MLP applied elementwise, with rescale in/out of u-space.
// Reads g_ubv, writes new u0 (= mlp_out * isd) into g_u0v.
__global__ void k_mlp(const float* __restrict__ emb,
                      const float* __restrict__ W1,
                      const float* __restrict__ b1,
                      const float* __restrict__ W2,
                      const float* __restrict__ b2) {
    __shared__ float sA[HID];           // W1 row 0
    __shared__ float sW2[HID];
    __shared__ float sC[FF][HID];       // b1[j] + sum_d emb[f,d]*W1[1+d,j]
    __shared__ float sB2;

    for (int t = threadIdx.x; t < FF * HID; t += blockDim.x) {
        int f = t / HID, j = t % HID;
        float c = b1[j];
        #pragma unroll
        for (int d = 0; d < EMB_DIM; d++)
            c += emb[f * EMB_DIM + d] * W1[(1 + d) * HID + j];
        sC[f][j] = c;
    }
    if (threadIdx.x < HID) {
        sA[threadIdx.x]  = W1[threadIdx.x];      // row 0
        sW2[threadIdx.x] = W2[threadIdx.x];
    }
    if (threadIdx.x == 0) sB2 = b2[0];
    __syncthreads();

    int idx = blockIdx.x * blockDim.x + threadIdx.x;
    if (idx >= NF) return;
    int n = idx >> 5;
    int f = idx & 31;
    float t = ((const float*)g_ubv)[idx] * g_sqd[n];
    float r = sB2;
    #pragma unroll
    for (int j = 0; j < HID; j++) {
        float h = fmaf(sA[j], t, sC[f][j]);
        r = fmaf(sW2[j], fmaxf(h, 0.0f), r);
    }
    ((float*)g_u0v)[idx] = r * g_isd[n];
}

// out[n,c] = bout[c] + sum_k (ub[n,k]*sqd[n]) * Wout[k,c]
__global__ void k_out(const float* __restrict__ Wout,
                      const float* __restrict__ bout,
                      float* __restrict__ out) {
    __shared__ float sW[FF * CC];
    __shared__ float sb[CC];
    for (int t = threadIdx.x; t < FF * CC; t += blockDim.x) sW[t] = Wout[t];
    if (threadIdx.x < CC) sb[threadIdx.x] = bout[threadIdx.x];
    __syncthreads();

    int tid = blockIdx.x * blockDim.x + threadIdx.x;
    if (tid >= NN * CC) return;
    int n = tid >> 4;
    int c = tid & 15;
    float sd = g_sqd[n];
    const float* u = (const float*)g_ubv;
    float acc = sb[c];
    #pragma unroll
    for (int k = 0; k < FF; k++)
        acc = fmaf(u[n * 32 + k] * sd, sW[k * CC + c], acc);
    out[tid] = acc;
}

// ---------------- launch ----------------

extern "C" void kernel_launch(void* const* d_in, const int* in_sizes, int n_in,
                              void* d_out, int out_size) {
    const float* x     = (const float*)d_in[0];
    const int*   edges = (const int*)d_in[1];       // int32 per harness dtype contract
    const float* emb   = (const float*)d_in[2];
    const float* W1    = (const float*)d_in[3];
    const float* b1    = (const float*)d_in[4];
    const float* W2    = (const float*)d_in[5];
    const float* b2    = (const float*)d_in[6];
    const float* Wout  = (const float*)d_in[7];
    const float* bout  = (const float*)d_in[8];
    float* out = (float*)d_out;

    const int TB = 256;
    int gE4 = (EE / 4 + TB - 1) / TB;
    int gNF = (NF + TB - 1) / TB;
    int gW  = (NN * 32 + TB - 1) / TB;   // warp-per-node grid
    int gNC = (NN * CC + TB - 1) / TB;

    // CSR build: counters zeroed via async memset, int4-vectorized passes
    void* cntp = nullptr; cudaGetSymbolAddress(&cntp, g_cnt);
    void* curp = nullptr; cudaGetSymbolAddress(&curp, g_cur);
    cudaMemsetAsync(cntp, 0, NN * sizeof(int));
    cudaMemsetAsync(curp, 0, NN * sizeof(int));
    k_count<<<gE4, TB>>>(edges);
    k_scan<<<1, 1024>>>();
    k_prep<<<gNF, TB>>>(x);
    k_fill<<<gE4, TB>>>(edges);

    // diffuse 1: u starts at u0 (sel 0); 10 conv steps ping-pong ua(1)/ub(2) -> ends in ub
    k_conv<<<gW, TB>>>(0, 1);
    for (int i = 1; i < DEPTH; i++) {
        int in_sel  = (i & 1) ? 1 : 2;
        int out_sel = (i & 1) ? 2 : 1;
        k_conv<<<gW, TB>>>(in_sel, out_sel);
    }

    // per-element MLP (reads g_ubv, writes new u0)
    k_mlp<<<gNF, TB>>>(emb, W1, b1, W2, b2);

    // diffuse 2
    k_conv<<<gW, TB>>>(0, 1);
    for (int i = 1; i < DEPTH; i++) {
        int in_sel  = (i & 1) ? 1 : 2;
        int out_sel = (i & 1) ? 2 : 1;
        k_conv<<<gW, TB>>>(in_sel, out_sel);
    }

    // output GEMM
    k_out<<<gNC, TB>>>(Wout, bout, out);
}